// round 6
// baseline (speedup 1.0000x reference)
#include <cuda_runtime.h>

// ROI-align-style pooling (RoiPoolingConv): img (1,128,128,1024) NHWC fp32,
// rois (1,256,4) [x,y,w,h] px, out (1,256,7,7,1024) fp32.
//
// R5: persistent software-pipelined blocks. 1184 blocks x 256 threads,
// grid-stride over 12544 bins (~11 bins/block). Each iteration prefetches
// the NEXT bin's params + 4 corner float4 loads while computing/storing the
// CURRENT bin: 8 LDG.128 in flight per warp steady-state, no per-bin
// pipeline refill, no wave-transition overhead.

#define POOL  7
#define NROIS 256
#define HH    128
#define WW    128
#define CC    1024
#define NBINS (NROIS * POOL * POOL)   // 12544
#define GRID  1184                    // 148 SMs * 8

// Per-bin params: 4 corner offsets (float4 units) + (tx, ty).
__device__ int4   g_offs[NBINS];
__device__ float2 g_ts[NBINS];

__global__ void setup_kernel(const float* __restrict__ rois)
{
    const int bin = blockIdx.x * blockDim.x + threadIdx.x;
    if (bin >= NBINS) return;

    const int roi = bin / (POOL * POOL);
    const int b49 = bin - roi * (POOL * POOL);
    const int iy  = b49 / POOL;
    const int ix  = b49 - iy * POOL;

    // roi = [x, y, w, h]; c = (int)(roi * 1/16)  (truncation, same as astype)
    const float4 r = reinterpret_cast<const float4*>(rois)[roi];
    const int x0 = (int)(r.x * 0.0625f);
    const int y0 = (int)(r.y * 0.0625f);
    const int w  = (int)(r.z * 0.0625f);
    const int h  = (int)(r.w * 0.0625f);

    // identical fp32 math to reference
    const float sy = (float)iy * ((float)h / (float)POOL);
    const float sx = (float)ix * ((float)w / (float)POOL);
    const float fy = floorf(sy);
    const float fx = floorf(sx);
    const float ty = sy - fy;
    const float tx = sx - fx;

    const int y_lo = (int)fy;
    const int x_lo = (int)fx;
    const int y_hi = min(y_lo + 1, max(h - 1, 0));
    const int x_hi = min(x_lo + 1, max(w - 1, 0));

    const int gy0 = min(max(y0 + y_lo, 0), HH - 1);
    const int gy1 = min(max(y0 + y_hi, 0), HH - 1);
    const int gx0 = min(max(x0 + x_lo, 0), WW - 1);
    const int gx1 = min(max(x0 + x_hi, 0), WW - 1);

    // Fold dead-weight (t==0) / clamp-identical hi corners onto lo corner:
    // duplicate addresses merge in L1tex, bit-exact result.
    const int ex = (tx != 0.0f && gx1 != gx0) ? gx1 : gx0;
    const int ey = (ty != 0.0f && gy1 != gy0) ? gy1 : gy0;

    const int c4 = CC / 4;
    int4 o;
    o.x = (gy0 * WW + gx0) * c4;
    o.y = (gy0 * WW + ex ) * c4;
    o.z = (ey  * WW + gx0) * c4;
    o.w = (ey  * WW + ex ) * c4;
    g_offs[bin] = o;
    g_ts[bin]   = make_float2(tx, ty);
}

__device__ __forceinline__ float4 lerp2(float4 a, float4 b, float4 c, float4 d,
                                        float tx, float ty)
{
    float4 r;
    float top, bot;
    top = a.x + tx * (b.x - a.x);
    bot = c.x + tx * (d.x - c.x);
    r.x = top + ty * (bot - top);
    top = a.y + tx * (b.y - a.y);
    bot = c.y + tx * (d.y - c.y);
    r.y = top + ty * (bot - top);
    top = a.z + tx * (b.z - a.z);
    bot = c.z + tx * (d.z - c.z);
    r.z = top + ty * (bot - top);
    top = a.w + tx * (b.w - a.w);
    bot = c.w + tx * (d.w - c.w);
    r.w = top + ty * (bot - top);
    return r;
}

__global__ __launch_bounds__(256, 4)
void roi_pool_kernel(const float* __restrict__ img,
                     float* __restrict__ out)
{
    const int t = threadIdx.x;                 // 0..255, one float4 lane
    const float4* __restrict__ imgv = reinterpret_cast<const float4*>(img);
    float4* __restrict__ outv = reinterpret_cast<float4*>(out);

    int bin = blockIdx.x;                      // GRID < NBINS always

    // ---- prologue: fill pipeline for first bin ----
    int4   o  = g_offs[bin];
    float2 tw = g_ts[bin];
    float4 a = imgv[o.x + t];
    float4 b = imgv[o.y + t];
    float4 c = imgv[o.z + t];
    float4 d = imgv[o.w + t];

    while (true) {
        const int nbin = bin + GRID;
        const bool has_next = (nbin < NBINS);

        int4 no; float2 ntw;
        float4 na, nb, nc, nd;
        if (has_next) {
            // prefetch next bin: params then 4 front-batched loads
            no  = g_offs[nbin];
            ntw = g_ts[nbin];
            na = imgv[no.x + t];
            nb = imgv[no.y + t];
            nc = imgv[no.z + t];
            nd = imgv[no.w + t];
        }

        // compute + store current (overlaps next bin's loads)
        const float4 r = lerp2(a, b, c, d, tw.x, tw.y);
        outv[(size_t)bin * (CC / 4) + t] = r;

        if (!has_next) break;
        bin = nbin; o = no; tw = ntw;
        a = na; b = nb; c = nc; d = nd;
    }
}

extern "C" void kernel_launch(void* const* d_in, const int* in_sizes, int n_in,
                              void* d_out, int out_size)
{
    const float* img  = (const float*)d_in[0];
    const float* rois = (const float*)d_in[1];
    if (n_in >= 2 && in_sizes[0] < in_sizes[1]) {
        img  = (const float*)d_in[1];
        rois = (const float*)d_in[0];
    }
    float* out = (float*)d_out;

    setup_kernel<<<(NBINS + 255) / 256, 256>>>(rois);
    roi_pool_kernel<<<GRID, 256>>>(img, out);
}